// round 2
// baseline (speedup 1.0000x reference)
#include <cuda_runtime.h>

// Shapes fixed by the problem
#define B_  32
#define Q_  900
#define C_  91
#define T_  30
#define BQ  (B_ * Q_)
#define BQC (B_ * Q_ * C_)
#define CSZ ((size_t)B_ * Q_ * Q_)   // 25,920,000

// Scratch (device globals — no allocation allowed)
__device__ float         g_cls[BQC];   // W_CLASS-weighted class cost table [B][Q][C]
__device__ int           g_label[BQ];
__device__ unsigned char g_mask[BQ];

// ---------------------------------------------------------------------------
// Fast reciprocal: magic constant + 2 Newton iterations (pure FMA pipe, no MUFU)
// rel err <= ~1.5e-5 for positive normal inputs
// ---------------------------------------------------------------------------
__device__ __forceinline__ float fast_rcp(float x) {
    float y = __int_as_float(0x7EF311C3 - __float_as_int(x));
    y = y * fmaf(-x, y, 2.0f);
    y = y * fmaf(-x, y, 2.0f);
    return y;
}

__device__ __forceinline__ float4 to_xyxy(float4 b) {
    float hw = 0.5f * b.z, hh = 0.5f * b.w;
    return make_float4(b.x - hw, b.y - hh, b.x + hw, b.y + hh);
}

// GIoU between two xyxy boxes with precomputed areas: iou - (area_c - union)/area_c
__device__ __forceinline__ float giou(float4 xa, float aa, float4 xb, float ab) {
    float w = fmaxf(fminf(xa.z, xb.z) - fmaxf(xa.x, xb.x), 0.0f);
    float h = fmaxf(fminf(xa.w, xb.w) - fmaxf(xa.y, xb.y), 0.0f);
    float inter = w * h;
    float uni = aa + ab - inter;
    float wc = fmaxf(fmaxf(xa.z, xb.z) - fminf(xa.x, xb.x), 0.0f);
    float hc = fmaxf(fmaxf(xa.w, xb.w) - fminf(xa.y, xb.y), 0.0f);
    float ac = wc * hc;
    return inter * fast_rcp(uni) - (ac - uni) * fast_rcp(ac);
}

// ---------------------------------------------------------------------------
// Kernel A: pseudo-label generation. One warp per (b, j_base).
//   - warp argmax over 91 logits (first-occurrence tie break)
//   - keep_prob = sigmoid(max) > 0.5
//   - keep_giou = all over 30 targets of (-giou > -0.1)
// ---------------------------------------------------------------------------
__global__ __launch_bounds__(256) void pseudo_kernel(
    const float*  __restrict__ logits_base,
    const float4* __restrict__ boxes_base,
    const float4* __restrict__ targets,
    float* __restrict__ mask_out, int write_mask)
{
    int w    = (blockIdx.x * blockDim.x + threadIdx.x) >> 5;
    int lane = threadIdx.x & 31;
    if (w >= BQ) return;
    int b = w / Q_;

    const float* lg = logits_base + (size_t)w * C_;
    float best = -1e30f; int bi = 0;
    for (int c = lane; c < C_; c += 32) {
        float v = lg[c];
        if (v > best) { best = v; bi = c; }
    }
    #pragma unroll
    for (int off = 16; off; off >>= 1) {
        float ov = __shfl_down_sync(0xffffffffu, best, off);
        int   oc = __shfl_down_sync(0xffffffffu, bi,   off);
        if (ov > best || (ov == best && oc < bi)) { best = ov; bi = oc; }
    }
    best = __shfl_sync(0xffffffffu, best, 0);
    bi   = __shfl_sync(0xffffffffu, bi,   0);

    float p = fast_rcp(1.0f + __expf(-best));
    bool keep_prob = (p > 0.5f);

    float4 bb = boxes_base[w];
    float4 xb = to_xyxy(bb);
    float  ab = (xb.z - xb.x) * (xb.w - xb.y);

    bool ok = true;
    if (lane < T_) {
        float4 tb = targets[b * T_ + lane];
        float4 xt = to_xyxy(tb);
        float  at = (xt.z - xt.x) * (xt.w - xt.y);
        float  g  = giou(xb, ab, xt, at);
        ok = ((-g) > -0.1f);
    }
    bool all_ok = __all_sync(0xffffffffu, ok);

    if (lane == 0) {
        unsigned char m = (keep_prob && all_ok) ? 1 : 0;
        g_label[w] = bi;
        g_mask[w]  = m;
        if (write_mask) mask_out[w] = (float)m;
    }
}

// ---------------------------------------------------------------------------
// Kernel B: focal class-cost table, pre-weighted by W_CLASS=2.
//   cls[b,i,c] = 2 * ( 0.25*(1-p)^2*(-log(p+eps)) - 0.75*p^2*(-log(1-p+eps)) )
// ---------------------------------------------------------------------------
__global__ __launch_bounds__(256) void cls_kernel(const float* __restrict__ logits)
{
    int idx = blockIdx.x * blockDim.x + threadIdx.x;
    if (idx >= BQC) return;
    float x   = logits[idx];
    float t   = __expf(-x);
    float p   = fast_rcp(1.0f + t);
    float omp = 1.0f - p;
    float pos = 0.25f * omp * omp * (-__logf(p   + 1e-8f));
    float neg = 0.75f * p   * p   * (-__logf(omp + 1e-8f));
    g_cls[idx] = 2.0f * (pos - neg);
}

// ---------------------------------------------------------------------------
// Kernel C: main 900x900 cost matrix.
//   Tile: 128 j (threadIdx.x, coalesced output) x 16 i (2 ty * 8 iters).
//   cls gather: i fixed per iteration -> per-warp addresses within one 364B row.
// ---------------------------------------------------------------------------
__global__ __launch_bounds__(256) void cost_kernel(
    const float4* __restrict__ boxes,       // current predictions
    const float4* __restrict__ boxes_base,  // pseudo targets
    float* __restrict__ out)
{
    __shared__ float4 sjb[128], sjx[128];
    __shared__ float  sja[128], sjm[128];
    __shared__ int    sjl[128];
    __shared__ float4 sib[16], six[16];
    __shared__ float  sia[16];

    int b  = blockIdx.z;
    int j0 = blockIdx.x * 128;
    int i0 = blockIdx.y * 16;
    int tid = threadIdx.y * 128 + threadIdx.x;

    if (tid < 128) {
        int j  = j0 + tid;
        int jc = (j < Q_) ? j : (Q_ - 1);
        float4 bb = boxes_base[b * Q_ + jc];
        float4 xb = to_xyxy(bb);
        sjb[tid] = bb;
        sjx[tid] = xb;
        sja[tid] = (xb.z - xb.x) * (xb.w - xb.y);
        sjl[tid] = g_label[b * Q_ + jc];
        sjm[tid] = g_mask[b * Q_ + jc] ? 1.0f : 0.0f;
    } else if (tid < 144) {
        int ii = tid - 128;
        int i  = i0 + ii;
        int ic = (i < Q_) ? i : (Q_ - 1);
        float4 bb = boxes[b * Q_ + ic];
        float4 xb = to_xyxy(bb);
        sib[ii] = bb;
        six[ii] = xb;
        sia[ii] = (xb.z - xb.x) * (xb.w - xb.y);
    }
    __syncthreads();

    int j = j0 + threadIdx.x;
    if (j >= Q_) return;

    float4 bj = sjb[threadIdx.x];
    float4 xj = sjx[threadIdx.x];
    float  aj = sja[threadIdx.x];
    int    lab = sjl[threadIdx.x];
    bool   mj  = (sjm[threadIdx.x] != 0.0f);

    size_t outb = (size_t)b * Q_ * Q_;

    #pragma unroll
    for (int k = 0; k < 8; ++k) {
        int ii = threadIdx.y * 8 + k;
        int i  = i0 + ii;
        if (i >= Q_) break;

        float cls = __ldg(&g_cls[((size_t)b * Q_ + i) * C_ + lab]);  // row broadcast per warp
        float4 bi = sib[ii];
        float4 xi = six[ii];
        float  ai = sia[ii];

        float l1 = fabsf(bi.x - bj.x) + fabsf(bi.y - bj.y)
                 + fabsf(bi.z - bj.z) + fabsf(bi.w - bj.w);
        float g  = giou(xi, ai, xj, aj);

        float cost = fmaf(5.0f, l1, cls) - 2.0f * g;
        out[outb + (size_t)i * Q_ + j] = mj ? cost : 1e9f;
    }
}

// ---------------------------------------------------------------------------
extern "C" void kernel_launch(void* const* d_in, const int* in_sizes, int n_in,
                              void* d_out, int out_size)
{
    const float*  pred_logits      = (const float*) d_in[0];
    const float4* pred_boxes       = (const float4*)d_in[1];
    const float*  pred_logits_base = (const float*) d_in[2];
    const float4* pred_boxes_base  = (const float4*)d_in[3];
    const float4* targets_boxes    = (const float4*)d_in[4];
    float* out = (float*)d_out;

    int write_mask = (out_size >= (int)(CSZ + BQ)) ? 1 : 0;

    // A: pseudo labels/mask. 8 warps/block -> 3600 blocks.
    pseudo_kernel<<<(BQ + 7) / 8, 256>>>(pred_logits_base, pred_boxes_base,
                                         targets_boxes, out + CSZ, write_mask);
    // B: class cost table.
    cls_kernel<<<(BQC + 255) / 256, 256>>>(pred_logits);
    // C: main cost matrix. grid (ceil(900/128)=8, ceil(900/16)=57, 32)
    dim3 grid(8, 57, B_), block(128, 2);
    cost_kernel<<<grid, block>>>(pred_boxes, pred_boxes_base, out);
}